// round 6
// baseline (speedup 1.0000x reference)
#include <cuda_runtime.h>
#include <cuda_bf16.h>
#include <cstdint>

// DNN_84026740179139: embedding-bag mean (50/row) + 3x [64x64 Linear + ReLU], fused.
// R6 = R5 with fixed f32x2 operand constraints (b64 via "l", not "d"/f64).
//   - RPB=32, 256 threads, grid 512 -> 4096 warps, occ ~42%.
//   - GEMM packs over ROW pairs: y2[d]=(y[r0][d],y[r1][d]); x2 is a direct LDS.64
//     from sXt; W stored DUPLICATED in shared ((w,w) pairs) so LDS.128 feeds FFMA2.
//     Inner k-step: 3 LDS + 4 FFMA2 for 8 MACs.
//   - Gather: sIdx staged in shared, 10 LDG.128 in flight.

#define BATCH   16384
#define DIMS    64
#define NNZ     50
#define RPB     32                  // rows per block
#define THREADS 256
#define GRID    (BATCH / RPB)       // 512
#define XTS     36                  // sXt row stride in floats (even -> 8B-aligned pairs)

typedef unsigned long long u64;

__device__ __forceinline__ u64 ffma2(u64 a, u64 b, u64 c) {
    u64 d;
    asm("fma.rn.f32x2 %0, %1, %2, %3;" : "=l"(d) : "l"(a), "l"(b), "l"(c));
    return d;
}
__device__ __forceinline__ u64 pack2(float x, float y) {
    u64 d;
    asm("mov.b64 %0, {%1, %2};" : "=l"(d) : "f"(x), "f"(y));
    return d;
}
__device__ __forceinline__ void unpack2(u64 d, float& x, float& y) {
    asm("mov.b64 {%0, %1}, %2;" : "=f"(x), "=f"(y) : "l"(d));
}

__global__ __launch_bounds__(THREADS) void dnn_fused6_kernel(
    const float* __restrict__ emb,
    const int*   __restrict__ fidx,
    const float* __restrict__ W0, const float* __restrict__ b0,
    const float* __restrict__ W1, const float* __restrict__ b1,
    const float* __restrict__ b2, const float* __restrict__ W2,
    float* __restrict__ out)
{
    __shared__ int   sIdx[RPB * NNZ];       // 6.4 KB
    __shared__ float sW2[DIMS * DIMS * 2];  // 32 KB : W duplicated, (w,w) pairs
    __shared__ float sXt[DIMS * XTS];       // 9.2 KB : x transposed, sXt[k*XTS + r]

    const int tid  = threadIdx.x;
    const int warp = tid >> 5;
    const int lane = tid & 31;

    // ---- Stage indices (coalesced int4) + W0 duplicated ----
    {
        const int4* src = (const int4*)(fidx + blockIdx.x * RPB * NNZ);
        int4*       dst = (int4*)sIdx;
        #pragma unroll
        for (int i = tid; i < (RPB * NNZ) / 4; i += THREADS)
            dst[i] = src[i];
    }
    {
        const float4* src = (const float4*)W0;   // i = k*16 + dg (dims 4dg..)
        float4*       dst = (float4*)sW2;        // row k = 32 float4
        #pragma unroll
        for (int s = 0; s < 4; s++) {
            const int i = tid + s * THREADS;
            const float4 w = src[i];
            dst[2 * i + 0] = make_float4(w.x, w.x, w.y, w.y);
            dst[2 * i + 1] = make_float4(w.z, w.z, w.w, w.w);
        }
    }
    __syncthreads();

    // ---- Gather + mean. Warp owns 4 rows; half-warp per row (float4 lanes).
    //      10 independent LDG.128 in flight (unroll 5 x 2 rows). ----
    const int half = lane >> 4;
    const int c    = lane & 15;
    const int lrowBase = warp * 4;                       // row within block

    const float4* emb4 = (const float4*)emb;
    float4 acc[2];
    acc[0] = make_float4(0.f, 0.f, 0.f, 0.f);
    acc[1] = make_float4(0.f, 0.f, 0.f, 0.f);

    #pragma unroll 1
    for (int i0 = 0; i0 < NNZ; i0 += 5) {
        #pragma unroll
        for (int u = 0; u < 5; u++) {
            #pragma unroll
            for (int j = 0; j < 2; j++) {
                const int lrow = lrowBase + 2 * j + half;
                const int id   = sIdx[lrow * NNZ + i0 + u];     // broadcast LDS
                const float4 v = __ldg(&emb4[(size_t)id * (DIMS / 4) + c]);
                acc[j].x += v.x; acc[j].y += v.y; acc[j].z += v.z; acc[j].w += v.w;
            }
        }
    }
    const float inv = 1.0f / (float)NNZ;
    #pragma unroll
    for (int j = 0; j < 2; j++) {
        const int r = lrowBase + 2 * j + half;
        sXt[(4 * c + 0) * XTS + r] = acc[j].x * inv;
        sXt[(4 * c + 1) * XTS + r] = acc[j].y * inv;
        sXt[(4 * c + 2) * XTS + r] = acc[j].z * inv;
        sXt[(4 * c + 3) * XTS + r] = acc[j].w * inv;
    }
    __syncthreads();

    // ---- MLP: 3 layers. Thread tile: 2 rows (packed) x 4 dims.
    //      tr = tid&15 -> rows 2tr, 2tr+1 ; td = tid>>4 -> dims 4td..4td+3 ----
    const int tr = tid & 15;
    const int td = tid >> 4;
    const int r0 = 2 * tr;
    const int d0 = 4 * td;

    const float* Wn[3] = {W0, W1, W2};
    const float* bn[3] = {b0, b1, b2};

    u64 y2[4];   // y2[d] = (y[r0][d0+d], y[r0+1][d0+d])

    #pragma unroll
    for (int l = 0; l < 3; l++) {
        {
            const float4 bias = __ldg((const float4*)(bn[l]) + td);
            y2[0] = pack2(bias.x, bias.x);
            y2[1] = pack2(bias.y, bias.y);
            y2[2] = pack2(bias.z, bias.z);
            y2[3] = pack2(bias.w, bias.w);
        }

        #pragma unroll 16
        for (int k = 0; k < DIMS; k++) {
            // (x[k][r0], x[k][r0+1]) : 16 distinct 8B addrs/warp, conflict-free
            const u64 x2 = *(const u64*)(sXt + k * XTS + r0);
            // duplicated weights: 2 LDS.128, 2 distinct addrs each (broadcast)
            const ulonglong2 wa = *(const ulonglong2*)(sW2 + k * (2 * DIMS) + 2 * d0);
            const ulonglong2 wb = *(const ulonglong2*)(sW2 + k * (2 * DIMS) + 2 * d0 + 4);
            y2[0] = ffma2(x2, wa.x, y2[0]);
            y2[1] = ffma2(x2, wa.y, y2[1]);
            y2[2] = ffma2(x2, wb.x, y2[2]);
            y2[3] = ffma2(x2, wb.y, y2[3]);
        }

        // ReLU (scalar unpack/repack; ALU-cheap, 4 values)
        #pragma unroll
        for (int d = 0; d < 4; d++) {
            float a, b;
            unpack2(y2[d], a, b);
            y2[d] = pack2(fmaxf(a, 0.f), fmaxf(b, 0.f));
        }

        if (l < 2) {
            __syncthreads();   // all reads of sXt(l)/sW2(l) complete
            // stage next layer's W duplicated
            {
                const float4* src = (const float4*)Wn[l + 1];
                float4*       dst = (float4*)sW2;
                #pragma unroll
                for (int s = 0; s < 4; s++) {
                    const int i = tid + s * THREADS;
                    const float4 w = src[i];
                    dst[2 * i + 0] = make_float4(w.x, w.x, w.y, w.y);
                    dst[2 * i + 1] = make_float4(w.z, w.z, w.w, w.w);
                }
            }
            // write back transposed: sXt[(d0+d)][r0..r0+1] = y2[d] (aligned 8B)
            #pragma unroll
            for (int d = 0; d < 4; d++)
                *(u64*)(sXt + (d0 + d) * XTS + r0) = y2[d];
            __syncthreads();
        }
    }

    // ---- Store output [B, 64]: two rows x 4 dims ----
    float o0[4], o1[4];
    #pragma unroll
    for (int d = 0; d < 4; d++) unpack2(y2[d], o0[d], o1[d]);
    const size_t gr0 = (size_t)(blockIdx.x * RPB + r0);
    *(float4*)(out + gr0       * DIMS + d0) = make_float4(o0[0], o0[1], o0[2], o0[3]);
    *(float4*)(out + (gr0 + 1) * DIMS + d0) = make_float4(o1[0], o1[1], o1[2], o1[3]);
}

extern "C" void kernel_launch(void* const* d_in, const int* in_sizes, int n_in,
                              void* d_out, int out_size)
{
    // Resolve inputs by element count:
    //   emb_table 6400000 f32; feature_indices 819200 i32 (first occurrence);
    //   W* 4096 f32 in order; b* 64 f32 in order.
    const float* emb  = nullptr;
    const int*   fidx = nullptr;
    const float* W[3] = {nullptr, nullptr, nullptr};
    const float* b[3] = {nullptr, nullptr, nullptr};
    int wi = 0, bi = 0;

    for (int i = 0; i < n_in; i++) {
        const int sz = in_sizes[i];
        if (sz == 100000 * 64) {
            emb = (const float*)d_in[i];
        } else if (sz == BATCH * NNZ) {
            if (!fidx) fidx = (const int*)d_in[i];
        } else if (sz == DIMS * DIMS) {
            if (wi < 3) W[wi++] = (const float*)d_in[i];
        } else if (sz == DIMS) {
            if (bi < 3) b[bi++] = (const float*)d_in[i];
        }
    }

    float* out = (float*)d_out;
    dnn_fused6_kernel<<<GRID, THREADS>>>(
        emb, fidx, W[0], b[0], W[1], b[1], b[2], W[2], out);
}

// round 7
// speedup vs baseline: 1.3138x; 1.3138x over previous
#include <cuda_runtime.h>
#include <cuda_bf16.h>
#include <cstdint>

// DNN_84026740179139: embedding-bag mean + 3x[64x64 Linear+ReLU].
// R7: TWO-KERNEL SPLIT.
//   K1 gather: 8192 warps (occ ~86%), warp = 2 rows, minimal gather wavefronts,
//      f32x2 adds, writes X[16384,64] to __device__ scratch.
//   K2 MLP: rows-packed fma.rn.f32x2; W in shared NON-duplicated (dup in regs via
//      mov.b64) -> same LDS bytes as best scalar kernel, half the FMA-pipe cycles.

#define BATCH   16384
#define DIMS    64
#define NNZ     50

typedef unsigned long long u64;

__device__ __forceinline__ u64 ffma2(u64 a, u64 b, u64 c) {
    u64 d; asm("fma.rn.f32x2 %0, %1, %2, %3;" : "=l"(d) : "l"(a), "l"(b), "l"(c)); return d;
}
__device__ __forceinline__ u64 add2(u64 a, u64 b) {
    u64 d; asm("add.rn.f32x2 %0, %1, %2;" : "=l"(d) : "l"(a), "l"(b)); return d;
}
__device__ __forceinline__ u64 mul2(u64 a, u64 b) {
    u64 d; asm("mul.rn.f32x2 %0, %1, %2;" : "=l"(d) : "l"(a), "l"(b)); return d;
}
__device__ __forceinline__ u64 pack2(float x, float y) {
    u64 d; asm("mov.b64 %0, {%1, %2};" : "=l"(d) : "f"(x), "f"(y)); return d;
}
__device__ __forceinline__ void unpack2(u64 d, float& x, float& y) {
    asm("mov.b64 {%0, %1}, %2;" : "=f"(x), "=f"(y) : "l"(d));
}

// 4MB scratch for pooled embeddings X[BATCH][DIMS]
__device__ float g_X[BATCH * DIMS];

// ================= K1 : gather + mean =================
#define K1_RPB   16                 // rows per block
#define K1_THR   256
#define K1_GRID  (BATCH / K1_RPB)   // 1024

__global__ __launch_bounds__(K1_THR) void gather_kernel(
    const float* __restrict__ emb,
    const int*   __restrict__ fidx)
{
    __shared__ int sIdx[K1_RPB * NNZ];     // 3.2 KB

    const int tid = threadIdx.x;
    // stage this block's 800 contiguous indices (200 int4)
    if (tid < (K1_RPB * NNZ) / 4)
        ((int4*)sIdx)[tid] = ((const int4*)(fidx + blockIdx.x * K1_RPB * NNZ))[tid];
    __syncthreads();

    const int warp = tid >> 5;
    const int lane = tid & 31;
    const int half = lane >> 4;            // which of the warp's 2 rows
    const int c    = lane & 15;            // 16B chunk within the row
    const int lrow = 2 * warp + half;      // row within block (0..15)

    const ulonglong2* emb2 = (const ulonglong2*)emb;  // 16B chunks; row = 16 chunks
    u64 a01 = 0ull, a23 = 0ull;            // (f0,f1),(f2,f3) accumulators

    #pragma unroll 1
    for (int i0 = 0; i0 < NNZ; i0 += 10) {
        #pragma unroll
        for (int u = 0; u < 10; u++) {
            const int id = sIdx[lrow * NNZ + i0 + u];          // broadcast LDS
            const ulonglong2 v = __ldg(&emb2[(size_t)id * 16 + c]);  // LDG.128
            a01 = add2(a01, v.x);
            a23 = add2(a23, v.y);
        }
    }

    const u64 inv2 = pack2(1.0f / NNZ, 1.0f / NNZ);
    a01 = mul2(a01, inv2);
    a23 = mul2(a23, inv2);

    float f0, f1, f2, f3;
    unpack2(a01, f0, f1);
    unpack2(a23, f2, f3);
    const int grow = blockIdx.x * K1_RPB + lrow;
    *(float4*)(g_X + (size_t)grow * DIMS + 4 * c) = make_float4(f0, f1, f2, f3);
}

// ================= K2 : 3x (Linear + ReLU) =================
#define K2_RPB   32                 // rows per block
#define K2_THR   128
#define K2_GRID  (BATCH / K2_RPB)   // 512
#define XTS      36                 // sXt row stride (mult of 4 -> 16B-aligned reads)

__global__ __launch_bounds__(K2_THR) void mlp_kernel(
    const float* __restrict__ W0, const float* __restrict__ b0,
    const float* __restrict__ W1, const float* __restrict__ b1,
    const float* __restrict__ b2, const float* __restrict__ W2,
    float* __restrict__ out)
{
    __shared__ float sW[DIMS * DIMS];      // 16 KB, staged per layer (NOT duplicated)
    __shared__ float sXt[DIMS * XTS];      // 9.2 KB, x transposed: sXt[k*XTS + r]

    const int tid = threadIdx.x;

    // ---- stage W0 ----
    {
        const float4* src = (const float4*)W0;
        float4*       dst = (float4*)sW;
        #pragma unroll
        for (int s = 0; s < 8; s++)
            dst[tid + s * K2_THR] = src[tid + s * K2_THR];
    }

    // ---- load X tile (coalesced) + transpose into sXt ----
    {
        const float4* X4 = (const float4*)(g_X + (size_t)blockIdx.x * K2_RPB * DIMS);
        #pragma unroll
        for (int s = 0; s < 4; s++) {
            const int idx = tid + s * K2_THR;       // 0..511
            const int row = idx >> 4;               // 0..31
            const int cg  = idx & 15;               // dims 4cg..4cg+3
            const float4 v = X4[idx];
            sXt[(4 * cg + 0) * XTS + row] = v.x;
            sXt[(4 * cg + 1) * XTS + row] = v.y;
            sXt[(4 * cg + 2) * XTS + row] = v.z;
            sXt[(4 * cg + 3) * XTS + row] = v.w;
        }
    }
    __syncthreads();

    // ---- GEMM: thread tile = 2 row-pairs x 4 dims. r0 = 4*(tid&7), d0 = 4*(tid>>3)
    const int r0 = 4 * (tid & 7);
    const int d0 = 4 * (tid >> 3);

    const float* Wn[3] = {W0, W1, W2};
    const float* bn[3] = {b0, b1, b2};

    u64 y2[2][4];    // y2[p][d] = (y[r0+2p][d0+d], y[r0+2p+1][d0+d])

    #pragma unroll
    for (int l = 0; l < 3; l++) {
        {
            const float4 bias = __ldg((const float4*)(bn[l]) + (d0 >> 2));
            const u64 bb[4] = {pack2(bias.x, bias.x), pack2(bias.y, bias.y),
                               pack2(bias.z, bias.z), pack2(bias.w, bias.w)};
            #pragma unroll
            for (int d = 0; d < 4; d++) { y2[0][d] = bb[d]; y2[1][d] = bb[d]; }
        }

        #pragma unroll 16
        for (int k = 0; k < DIMS; k++) {
            // (x[k][r0..r0+3]) as two packed pairs: 1 LDS.128, conflict-free
            const ulonglong2 xx = *(const ulonglong2*)(sXt + k * XTS + r0);
            // scalar weights: 1 LDS.128, 4 distinct addrs (broadcast)
            const float4 w = *(const float4*)(sW + k * DIMS + d0);
            // duplicate in registers (alu pipe, which is idle)
            const u64 w2[4] = {pack2(w.x, w.x), pack2(w.y, w.y),
                               pack2(w.z, w.z), pack2(w.w, w.w)};
            #pragma unroll
            for (int d = 0; d < 4; d++) {
                y2[0][d] = ffma2(xx.x, w2[d], y2[0][d]);
                y2[1][d] = ffma2(xx.y, w2[d], y2[1][d]);
            }
        }

        // ReLU
        #pragma unroll
        for (int p = 0; p < 2; p++)
            #pragma unroll
            for (int d = 0; d < 4; d++) {
                float a, b;
                unpack2(y2[p][d], a, b);
                y2[p][d] = pack2(fmaxf(a, 0.f), fmaxf(b, 0.f));
            }

        if (l < 2) {
            __syncthreads();
            // stage next layer's W
            {
                const float4* src = (const float4*)Wn[l + 1];
                float4*       dst = (float4*)sW;
                #pragma unroll
                for (int s = 0; s < 8; s++)
                    dst[tid + s * K2_THR] = src[tid + s * K2_THR];
            }
            // write y back transposed (aligned 8B stores)
            #pragma unroll
            for (int p = 0; p < 2; p++)
                #pragma unroll
                for (int d = 0; d < 4; d++)
                    *(u64*)(sXt + (d0 + d) * XTS + r0 + 2 * p) = y2[p][d];
            __syncthreads();
        }
    }

    // ---- store out[B,64]: 4 rows x 4 dims ----
    #pragma unroll
    for (int p = 0; p < 2; p++) {
        float a0, b0_, a1, b1_, a2, b2_, a3, b3_;
        unpack2(y2[p][0], a0, b0_);
        unpack2(y2[p][1], a1, b1_);
        unpack2(y2[p][2], a2, b2_);
        unpack2(y2[p][3], a3, b3_);
        const size_t gr = (size_t)blockIdx.x * K2_RPB + r0 + 2 * p;
        *(float4*)(out + gr       * DIMS + d0) = make_float4(a0, a1, a2, a3);
        *(float4*)(out + (gr + 1) * DIMS + d0) = make_float4(b0_, b1_, b2_, b3_);
    }
}

extern "C" void kernel_launch(void* const* d_in, const int* in_sizes, int n_in,
                              void* d_out, int out_size)
{
    // Resolve inputs by element count:
    //   emb_table 6400000 f32; feature_indices 819200 i32 (first occurrence);
    //   W* 4096 f32 in order; b* 64 f32 in order.
    const float* emb  = nullptr;
    const int*   fidx = nullptr;
    const float* W[3] = {nullptr, nullptr, nullptr};
    const float* b[3] = {nullptr, nullptr, nullptr};
    int wi = 0, bi = 0;

    for (int i = 0; i < n_in; i++) {
        const int sz = in_sizes[i];
        if (sz == 100000 * 64) {
            emb = (const float*)d_in[i];
        } else if (sz == BATCH * NNZ) {
            if (!fidx) fidx = (const int*)d_in[i];
        } else if (sz == DIMS * DIMS) {
            if (wi < 3) W[wi++] = (const float*)d_in[i];
        } else if (sz == DIMS) {
            if (bi < 3) b[bi++] = (const float*)d_in[i];
        }
    }

    float* out = (float*)d_out;
    gather_kernel<<<K1_GRID, K1_THR>>>(emb, fidx);
    mlp_kernel<<<K2_GRID, K2_THR>>>(W[0], b[0], W[1], b[1], b[2], W[2], out);
}